// round 10
// baseline (speedup 1.0000x reference)
#include <cuda_runtime.h>
#include <cuda_fp16.h>
#include <cstdint>

#define DEV_INLINE __device__ __forceinline__

// ---------------- problem sizes ----------------
static constexpr int kB = 16384;
static constexpr int kD = 1024;
static constexpr int kU = 128;

static constexpr int PAIR_BYTES = 128 * 128;     // 16384 (128 rows x 128B)

// ---------------- spline kernel tiling ----------------
static constexpr int S_DC  = 32;                 // K per chunk
static constexpr int S_NCH = kD / S_DC;          // 32
static constexpr int S_AREG = 3 * PAIR_BYTES;    // 49152 A region (3 pairs)
static constexpr int S_BUF  = 2 * S_AREG;        // 98304 (A + W)
static constexpr int S_SMEM = 2 * S_BUF;         // 196608 double buffered
static constexpr int S_W_U4 = 3 * PAIR_BYTES / 16;  // 3072 uint4/chunk

// ---------------- base kernel tiling ----------------
static constexpr int B_DC  = 64;                 // K per chunk
static constexpr int B_NCH = kD / B_DC;          // 16
static constexpr int B_AREG = PAIR_BYTES;        // 16384
static constexpr int B_BUF  = 2 * B_AREG;        // 32768
static constexpr int B_SMEM = 2 * B_BUF;         // 65536
static constexpr int B_W_U4 = PAIR_BYTES / 16;   // 1024 uint4/chunk

// packed weights
__device__ __half g_WbPack[16 * 8192];           // base:   [c16][n128][k64] SW128
__device__ __half g_WsPack[96 * 8192];           // spline: [c32][p3][n128][64h] SW128

// ---------------- PTX helpers ----------------
DEV_INLINE uint32_t smem_u32(const void* p) {
    uint32_t a;
    asm("{ .reg .u64 t; cvta.to.shared.u64 t, %1; cvt.u32.u64 %0, t; }" : "=r"(a) : "l"(p));
    return a;
}

#define LDSM_X4(r, addr)                                                        \
    asm volatile("ldmatrix.sync.aligned.m8n8.x4.shared.b16 {%0,%1,%2,%3}, [%4];"\
                 : "=r"((r)[0]), "=r"((r)[1]), "=r"((r)[2]), "=r"((r)[3])       \
                 : "r"(addr))

DEV_INLINE void mma16816(float* d, const uint32_t* a, uint32_t b0, uint32_t b1) {
    asm volatile(
        "mma.sync.aligned.m16n8k16.row.col.f32.f16.f16.f32 "
        "{%0,%1,%2,%3}, {%4,%5,%6,%7}, {%8,%9}, {%0,%1,%2,%3};"
        : "+f"(d[0]), "+f"(d[1]), "+f"(d[2]), "+f"(d[3])
        : "r"(a[0]), "r"(a[1]), "r"(a[2]), "r"(a[3]), "r"(b0), "r"(b1));
}

DEV_INLINE void cp_async16(uint32_t smem_dst, const void* gsrc) {
    asm volatile("cp.async.cg.shared.global [%0], [%1], 16;"
                 :: "r"(smem_dst), "l"(gsrc) : "memory");
}
DEV_INLINE void cp_async_commit() { asm volatile("cp.async.commit_group;" ::: "memory"); }
DEV_INLINE void cp_async_wait_all() { asm volatile("cp.async.wait_group 0;" ::: "memory"); }

// ---------------- weight prep ----------------
__global__ void kan_prep_weights(const float* __restrict__ bw,
                                 const float* __restrict__ sw) {
    int idx = blockIdx.x * blockDim.x + threadIdx.x;
    if (idx < 131072) {
        int k = idx & 63, n = (idx >> 6) & 127, c = idx >> 13;
        int i = c * 64 + k;
        unsigned off = (unsigned)(n * 128 + k * 2);
        unsigned swz = off ^ ((off >> 3) & 0x70);
        g_WbPack[(size_t)c * 8192 + (swz >> 1)] = __float2half(bw[i * kU + n]);
    } else {
        int j  = idx - 131072;
        int hw = j & 63, n = (j >> 6) & 127, t3 = j >> 13;  // t3 = c*3+p
        int p  = t3 % 3, c = t3 / 3;
        int slo = hw >> 5, k = hw & 31;
        int g = p * 2 + slo;
        int i = c * 32 + k;
        unsigned off = (unsigned)(n * 128 + slo * 64 + k * 2);
        unsigned swz = off ^ ((off >> 3) & 0x70);
        float v = (g < 5) ? sw[(size_t)(i * kU + n) * 8 + g] : 0.f;
        g_WsPack[(size_t)t3 * 8192 + (swz >> 1)] = __float2half(v);
    }
}

// ---- 64x32 warp-tile load / mma macros ----
// A: 4x LDSM.x4 (mb 0..3), B: 2x LDSM.x4 (k-halves). Addresses precomputed.
#define LD_FRAGS64x32(OFF, J, FA, FB) do {                                      \
    LDSM_X4(&(FB)[0],  bAddr[2 * (J) + 0] + (OFF));                             \
    LDSM_X4(&(FB)[4],  bAddr[2 * (J) + 1] + (OFF));                             \
    LDSM_X4(&(FA)[0],  aAddr[0][J] + (OFF));                                    \
    LDSM_X4(&(FA)[4],  aAddr[1][J] + (OFF));                                    \
    LDSM_X4(&(FA)[8],  aAddr[2][J] + (OFF));                                    \
    LDSM_X4(&(FA)[12], aAddr[3][J] + (OFF));                                    \
} while (0)

#define MMA_FRAGS64x32(FA, FB) do {                                             \
    _Pragma("unroll")                                                           \
    for (int mb_ = 0; mb_ < 4; ++mb_)                                           \
        _Pragma("unroll")                                                       \
        for (int nb_ = 0; nb_ < 4; ++nb_)                                       \
            mma16816(acc[mb_][nb_], &(FA)[mb_ * 4], (FB)[nb_], (FB)[4 + nb_]);  \
} while (0)

// =======================================================================
// BASE kernel: out = SiLU(x @ Wb). 8 warps, merged produce+consume.
// =======================================================================
__global__ void __launch_bounds__(256, 1)
kan_base_kernel(const float* __restrict__ x, float* __restrict__ out) {
    extern __shared__ char smem[];
    const uint32_t smem_base = smem_u32(smem);
    const int tid  = threadIdx.x;
    const int wid  = tid >> 5;
    const int lane = tid & 31;
    const int row_base = blockIdx.x * 128;

    // consumer: 2x4 grid of 64x32 tiles
    const int mi = wid & 1;
    const int ni = wid >> 1;

    float acc[4][4][4];
    #pragma unroll
    for (int a = 0; a < 4; ++a)
        #pragma unroll
        for (int b = 0; b < 4; ++b)
            #pragma unroll
            for (int j = 0; j < 4; ++j) acc[a][b][j] = 0.f;

    const int aRowLocal  = (lane & 7) + ((lane >> 3) & 1) * 8;
    const uint32_t kbAhi = ((lane >> 4) & 1) * 16;
    uint32_t aAddr[4][4];
    #pragma unroll
    for (int mb = 0; mb < 4; ++mb) {
        int r = mi * 64 + mb * 16 + aRowLocal;
        uint32_t base = smem_base + (uint32_t)(r * 128);
        uint32_t ax   = (uint32_t)((r & 7) << 4);
        #pragma unroll
        for (int j = 0; j < 4; ++j)
            aAddr[mb][j] = base + (((uint32_t)(j * 32) + kbAhi) ^ ax);
    }
    uint32_t bAddr[8];
    {
        int rB = ni * 32 + lane;
        uint32_t base = smem_base + (uint32_t)B_AREG + (uint32_t)(rB * 128);
        uint32_t bx   = (uint32_t)((rB & 7) << 4);
        #pragma unroll
        for (int jb = 0; jb < 8; ++jb)
            bAddr[jb] = base + (((uint32_t)(jb * 16)) ^ bx);
    }

    // producer mapping: row pr, col-half hf (32 cols of the 64-col chunk)
    const int pr = tid & 127;
    const int hf = tid >> 7;
    const float* xp = x + (size_t)(row_base + pr) * kD + hf * 32;
    const unsigned rowOff = (unsigned)(pr * 128 + hf * 64);
    const unsigned rXor   = (unsigned)((pr & 7) << 4);

    float4 xq[8];
    auto loadX = [&](int c) {
        const float* p = xp + c * B_DC;
        #pragma unroll
        for (int j = 0; j < 8; ++j)
            xq[j] = *reinterpret_cast<const float4*>(p + j * 4);
    };
    auto produce2 = [&](int g0, uint32_t bufOff) {   // two 8-elem groups
        #pragma unroll
        for (int g = g0; g < g0 + 2; ++g) {
            union { __half2 h2[4]; uint4 u4; } st;
            st.h2[0] = __floats2half2_rn(xq[2*g].x,   xq[2*g].y);
            st.h2[1] = __floats2half2_rn(xq[2*g].z,   xq[2*g].w);
            st.h2[2] = __floats2half2_rn(xq[2*g+1].x, xq[2*g+1].y);
            st.h2[3] = __floats2half2_rn(xq[2*g+1].z, xq[2*g+1].w);
            unsigned off = rowOff + (unsigned)(g * 16);
            unsigned swz = off ^ rXor;
            *reinterpret_cast<uint4*>(smem + bufOff + swz) = st.u4;
        }
    };
    auto copyW = [&](int c, uint32_t bufOff) {
        const char* src = reinterpret_cast<const char*>(g_WbPack) + (size_t)c * 16384;
        #pragma unroll
        for (int j = 0; j < B_W_U4 / 256; ++j) {  // 4 per thread
            int i = tid + j * 256;
            cp_async16(smem_base + bufOff + B_AREG + i * 16, src + i * 16);
        }
        cp_async_commit();
    };

    // prologue: chunk 0 -> buffer 0
    copyW(0, 0);
    loadX(0);
    produce2(0, 0);
    produce2(2, 0);
    cp_async_wait_all();
    __syncthreads();

    uint32_t fa0[16], fa1[16], fb0[8], fb1[8];
    for (int c = 0; c < B_NCH; ++c) {
        const uint32_t bo = (uint32_t)((c & 1) * B_BUF);
        const uint32_t bn = (uint32_t)(((c + 1) & 1) * B_BUF);
        const bool pf = (c + 1 < B_NCH);
        if (pf) { copyW(c + 1, bn); loadX(c + 1); }

        LD_FRAGS64x32(bo, 0, fa0, fb0);
        LD_FRAGS64x32(bo, 1, fa1, fb1);  MMA_FRAGS64x32(fa0, fb0);
        LD_FRAGS64x32(bo, 2, fa0, fb0);  MMA_FRAGS64x32(fa1, fb1);
        if (pf) produce2(0, bn);
        LD_FRAGS64x32(bo, 3, fa1, fb1);  MMA_FRAGS64x32(fa0, fb0);
        if (pf) produce2(2, bn);
                                         MMA_FRAGS64x32(fa1, fb1);
        cp_async_wait_all();
        __syncthreads();
    }

    // epilogue: SiLU, store
    const int colBase = ni * 32 + (lane & 3) * 2;
    #pragma unroll
    for (int mb = 0; mb < 4; ++mb) {
        int row0 = row_base + mi * 64 + mb * 16 + (lane >> 2);
        #pragma unroll
        for (int nb = 0; nb < 4; ++nb) {
            int col = colBase + nb * 8;
            float z0 = acc[mb][nb][0], z1 = acc[mb][nb][1];
            float z2 = acc[mb][nb][2], z3 = acc[mb][nb][3];
            float2 v0, v1;
            v0.x = __fdividef(z0, 1.f + __expf(-z0));
            v0.y = __fdividef(z1, 1.f + __expf(-z1));
            v1.x = __fdividef(z2, 1.f + __expf(-z2));
            v1.y = __fdividef(z3, 1.f + __expf(-z3));
            *reinterpret_cast<float2*>(out + (size_t)row0 * kU + col)       = v0;
            *reinterpret_cast<float2*>(out + (size_t)(row0 + 8) * kU + col) = v1;
        }
    }
}

// =======================================================================
// SPLINE kernel: out += einsum(rbf(x), Ws). 8 warps, merged.
// =======================================================================
__global__ void __launch_bounds__(256, 1)
kan_spline_kernel(const float* __restrict__ x, float* __restrict__ out) {
    extern __shared__ char smem[];
    const uint32_t smem_base = smem_u32(smem);
    const int tid  = threadIdx.x;
    const int wid  = tid >> 5;
    const int lane = tid & 31;
    const int row_base = blockIdx.x * 128;

    const float E375p = 42.52108200006278f;    // e^{3.75}
    const float E125p = 3.4903429574597902f;   // e^{1.25}
    const float E125m = 0.2865047968601901f;   // e^{-1.25}
    const float E375m = 0.023517745856009107f; // e^{-3.75}

    const int mi = wid & 1;
    const int ni = wid >> 1;

    float acc[4][4][4];
    #pragma unroll
    for (int a = 0; a < 4; ++a)
        #pragma unroll
        for (int b = 0; b < 4; ++b)
            #pragma unroll
            for (int j = 0; j < 4; ++j) acc[a][b][j] = 0.f;

    const int aRowLocal  = (lane & 7) + ((lane >> 3) & 1) * 8;
    const uint32_t kbAhi = ((lane >> 4) & 1) * 16;
    uint32_t aAddr[4][4];
    #pragma unroll
    for (int mb = 0; mb < 4; ++mb) {
        int r = mi * 64 + mb * 16 + aRowLocal;
        uint32_t base = smem_base + (uint32_t)(r * 128);
        uint32_t ax   = (uint32_t)((r & 7) << 4);
        #pragma unroll
        for (int j = 0; j < 4; ++j)
            aAddr[mb][j] = base + (((uint32_t)(j * 32) + kbAhi) ^ ax);
    }
    uint32_t bAddr[8];
    {
        int rB = ni * 32 + lane;
        uint32_t base = smem_base + (uint32_t)S_AREG + (uint32_t)(rB * 128);
        uint32_t bx   = (uint32_t)((rB & 7) << 4);
        #pragma unroll
        for (int jb = 0; jb < 8; ++jb)
            bAddr[jb] = base + (((uint32_t)(jb * 16)) ^ bx);
    }

    // producer mapping: row pr, col-half hf (16 cols of the 32-col chunk)
    const int pr = tid & 127;
    const int hf = tid >> 7;
    const float* xp = x + (size_t)(row_base + pr) * kD + hf * 16;
    const unsigned rowOff = (unsigned)(pr * 128 + hf * 32);
    const unsigned rXor   = (unsigned)((pr & 7) << 4);

    float4 xq[4];
    auto loadX = [&](int c) {
        const float* p = xp + c * S_DC;
        #pragma unroll
        for (int j = 0; j < 4; ++j)
            xq[j] = *reinterpret_cast<const float4*>(p + j * 4);
    };
    // one 8-element group g (0 or 1): 5 rbf streams, 5 STS.128
    auto produce_group = [&](int g, uint32_t bufOff) {
        float xs[8];
        xs[0]=xq[2*g].x;   xs[1]=xq[2*g].y;   xs[2]=xq[2*g].z;   xs[3]=xq[2*g].w;
        xs[4]=xq[2*g+1].x; xs[5]=xq[2*g+1].y; xs[6]=xq[2*g+1].z; xs[7]=xq[2*g+1].w;
        union { __half2 h2[4]; uint4 u4; } st[5];
        #pragma unroll
        for (int e = 0; e < 8; e += 2) {
            float a0 = xs[e] + 1.f, a1 = xs[e+1] + 1.f;
            float y0a = __expf(-5.f * a0 * a0);
            float y0b = __expf(-5.f * a1 * a1);
            float ta  = __expf(5.f * xs[e]);
            float tb  = __expf(5.f * xs[e+1]);
            float y1a = y0a * ta * E375p, y1b = y0b * tb * E375p;
            float y2a = y1a * ta * E125p, y2b = y1b * tb * E125p;
            float y3a = y2a * ta * E125m, y3b = y2b * tb * E125m;
            float y4a = y3a * ta * E375m, y4b = y3b * tb * E375m;
            int j = e >> 1;
            st[0].h2[j] = __floats2half2_rn(y0a, y0b);
            st[1].h2[j] = __floats2half2_rn(y1a, y1b);
            st[2].h2[j] = __floats2half2_rn(y2a, y2b);
            st[3].h2[j] = __floats2half2_rn(y3a, y3b);
            st[4].h2[j] = __floats2half2_rn(y4a, y4b);
        }
        #pragma unroll
        for (int s = 0; s < 5; ++s) {
            int p = s >> 1, slo = s & 1;
            unsigned off = (unsigned)(pr * 128 + slo * 64 + hf * 32 + g * 16);
            unsigned swz = off ^ rXor;
            *reinterpret_cast<uint4*>(smem + bufOff + p * PAIR_BYTES + swz) = st[s].u4;
        }
    };
    auto copyW = [&](int c, uint32_t bufOff) {
        const char* src = reinterpret_cast<const char*>(g_WsPack) +
                          (size_t)c * (3 * 16384);
        #pragma unroll
        for (int j = 0; j < S_W_U4 / 256; ++j) {  // 12 per thread
            int i = tid + j * 256;
            cp_async16(smem_base + bufOff + S_AREG + i * 16, src + i * 16);
        }
        cp_async_commit();
    };

    // prologue
    copyW(0, 0);
    loadX(0);
    produce_group(0, 0);
    produce_group(1, 0);
    cp_async_wait_all();
    __syncthreads();

    // step T: s = T/2 (stream 0..4), kk = T&1; pair p = s>>1; j = (s&1)*2+kk
#define S_LD(T, FA, FB) do {                                                    \
    constexpr int s_ = (T) / 2, kk_ = (T) & 1;                                  \
    constexpr uint32_t pOff_ = (uint32_t)((s_ >> 1) * PAIR_BYTES);              \
    constexpr int j_ = (s_ & 1) * 2 + kk_;                                      \
    LD_FRAGS64x32(bo + pOff_, j_, FA, FB);                                      \
} while (0)

    uint32_t fa0[16], fa1[16], fb0[8], fb1[8];
    for (int c = 0; c < S_NCH; ++c) {
        const uint32_t bo = (uint32_t)((c & 1) * S_BUF);
        const uint32_t bn = (uint32_t)(((c + 1) & 1) * S_BUF);
        const bool pf = (c + 1 < S_NCH);
        if (pf) { copyW(c + 1, bn); loadX(c + 1); }

        S_LD(0, fa0, fb0);
        S_LD(1, fa1, fb1);  MMA_FRAGS64x32(fa0, fb0);
        S_LD(2, fa0, fb0);  MMA_FRAGS64x32(fa1, fb1);
        S_LD(3, fa1, fb1);  MMA_FRAGS64x32(fa0, fb0);
        S_LD(4, fa0, fb0);  MMA_FRAGS64x32(fa1, fb1);
        if (pf) produce_group(0, bn);
        S_LD(5, fa1, fb1);  MMA_FRAGS64x32(fa0, fb0);
        S_LD(6, fa0, fb0);  MMA_FRAGS64x32(fa1, fb1);
        S_LD(7, fa1, fb1);  MMA_FRAGS64x32(fa0, fb0);
        S_LD(8, fa0, fb0);  MMA_FRAGS64x32(fa1, fb1);
        if (pf) produce_group(1, bn);
        S_LD(9, fa1, fb1);  MMA_FRAGS64x32(fa0, fb0);
                            MMA_FRAGS64x32(fa1, fb1);
        cp_async_wait_all();
        __syncthreads();
    }
#undef S_LD

    // epilogue: out += spline
    const int colBase = ni * 32 + (lane & 3) * 2;
    #pragma unroll
    for (int mb = 0; mb < 4; ++mb) {
        int row0 = row_base + mi * 64 + mb * 16 + (lane >> 2);
        #pragma unroll
        for (int nb = 0; nb < 4; ++nb) {
            int col = colBase + nb * 8;
            float2* p0 = reinterpret_cast<float2*>(out + (size_t)row0 * kU + col);
            float2* p1 = reinterpret_cast<float2*>(out + (size_t)(row0 + 8) * kU + col);
            float2 v0 = *p0, v1 = *p1;
            v0.x += acc[mb][nb][0]; v0.y += acc[mb][nb][1];
            v1.x += acc[mb][nb][2]; v1.y += acc[mb][nb][3];
            *p0 = v0; *p1 = v1;
        }
    }
}

// ---------------- launch ----------------
extern "C" void kernel_launch(void* const* d_in, const int* in_sizes, int n_in,
                              void* d_out, int out_size) {
    (void)in_sizes; (void)n_in; (void)out_size;
    const float* x  = (const float*)d_in[0];
    const float* bw = (const float*)d_in[1];
    const float* sw = (const float*)d_in[2];
    float* out = (float*)d_out;

    cudaFuncSetAttribute(kan_base_kernel,
                         cudaFuncAttributeMaxDynamicSharedMemorySize, B_SMEM);
    cudaFuncSetAttribute(kan_spline_kernel,
                         cudaFuncAttributeMaxDynamicSharedMemorySize, S_SMEM);

    kan_prep_weights<<<(131072 + 786432) / 256, 256>>>(bw, sw);
    kan_base_kernel<<<kB / 128, 256, B_SMEM>>>(x, out);
    kan_spline_kernel<<<kB / 128, 256, S_SMEM>>>(x, out);
}

// round 11
// speedup vs baseline: 1.2269x; 1.2269x over previous
#include <cuda_runtime.h>
#include <cuda_fp16.h>
#include <cstdint>

#define DEV_INLINE __device__ __forceinline__

// ---------------- problem sizes ----------------
static constexpr int kB = 16384;
static constexpr int kD = 1024;
static constexpr int kU = 128;

static constexpr int PAIR_BYTES = 128 * 128;     // 16384 (128 rows x 128B)

// ---------------- spline kernel tiling ----------------
static constexpr int S_DC  = 32;                 // K per chunk
static constexpr int S_NCH = kD / S_DC;          // 32
static constexpr int S_AREG = 3 * PAIR_BYTES;    // 49152 A region (3 pairs)
static constexpr int S_BUF  = 2 * S_AREG;        // 98304 (A + W)
static constexpr int S_SMEM = 2 * S_BUF;         // 196608 double buffered
static constexpr int S_W_U4 = 3 * PAIR_BYTES / 16;  // 3072 uint4/chunk

// ---------------- base kernel tiling ----------------
static constexpr int B_DC  = 64;                 // K per chunk
static constexpr int B_NCH = kD / B_DC;          // 16
static constexpr int B_AREG = PAIR_BYTES;        // 16384
static constexpr int B_BUF  = 2 * B_AREG;        // 32768
static constexpr int B_SMEM = 2 * B_BUF;         // 65536
static constexpr int B_W_U4 = PAIR_BYTES / 16;   // 1024 uint4/chunk

static constexpr int NTHREADS = 384;   // 4 producer warps (0-3) + 8 consumer warps (4-11)

// packed weights
__device__ __half g_WbPack[16 * 8192];           // base:   [c16][n128][k64] SW128
__device__ __half g_WsPack[96 * 8192];           // spline: [c32][p3][n128][64h] SW128

// ---------------- PTX helpers ----------------
DEV_INLINE uint32_t smem_u32(const void* p) {
    uint32_t a;
    asm("{ .reg .u64 t; cvta.to.shared.u64 t, %1; cvt.u32.u64 %0, t; }" : "=r"(a) : "l"(p));
    return a;
}

#define LDSM_X4(r, addr)                                                        \
    asm volatile("ldmatrix.sync.aligned.m8n8.x4.shared.b16 {%0,%1,%2,%3}, [%4];"\
                 : "=r"((r)[0]), "=r"((r)[1]), "=r"((r)[2]), "=r"((r)[3])       \
                 : "r"(addr))

DEV_INLINE void mma16816(float* d, const uint32_t* a, uint32_t b0, uint32_t b1) {
    asm volatile(
        "mma.sync.aligned.m16n8k16.row.col.f32.f16.f16.f32 "
        "{%0,%1,%2,%3}, {%4,%5,%6,%7}, {%8,%9}, {%0,%1,%2,%3};"
        : "+f"(d[0]), "+f"(d[1]), "+f"(d[2]), "+f"(d[3])
        : "r"(a[0]), "r"(a[1]), "r"(a[2]), "r"(a[3]), "r"(b0), "r"(b1));
}

DEV_INLINE void cp_async16(uint32_t smem_dst, const void* gsrc) {
    asm volatile("cp.async.cg.shared.global [%0], [%1], 16;"
                 :: "r"(smem_dst), "l"(gsrc) : "memory");
}
DEV_INLINE void cp_async_commit() { asm volatile("cp.async.commit_group;" ::: "memory"); }
DEV_INLINE void cp_async_wait_all() { asm volatile("cp.async.wait_group 0;" ::: "memory"); }

// ---------------- weight prep ----------------
__global__ void kan_prep_weights(const float* __restrict__ bw,
                                 const float* __restrict__ sw) {
    int idx = blockIdx.x * blockDim.x + threadIdx.x;
    if (idx < 131072) {
        int k = idx & 63, n = (idx >> 6) & 127, c = idx >> 13;
        int i = c * 64 + k;
        unsigned off = (unsigned)(n * 128 + k * 2);
        unsigned swz = off ^ ((off >> 3) & 0x70);
        g_WbPack[(size_t)c * 8192 + (swz >> 1)] = __float2half(bw[i * kU + n]);
    } else {
        int j  = idx - 131072;
        int hw = j & 63, n = (j >> 6) & 127, t3 = j >> 13;  // t3 = c*3+p
        int p  = t3 % 3, c = t3 / 3;
        int slo = hw >> 5, k = hw & 31;
        int g = p * 2 + slo;
        int i = c * 32 + k;
        unsigned off = (unsigned)(n * 128 + slo * 64 + k * 2);
        unsigned swz = off ^ ((off >> 3) & 0x70);
        float v = (g < 5) ? sw[(size_t)(i * kU + n) * 8 + g] : 0.f;
        g_WsPack[(size_t)t3 * 8192 + (swz >> 1)] = __float2half(v);
    }
}

// ---- 64x32 warp-tile load / mma macros (single accumulator set) ----
#define LD_FRAGS64x32(OFF, J, FA, FB) do {                                      \
    LDSM_X4(&(FB)[0],  bAddr[2 * (J) + 0] + (OFF));                             \
    LDSM_X4(&(FB)[4],  bAddr[2 * (J) + 1] + (OFF));                             \
    LDSM_X4(&(FA)[0],  aAddr[0][J] + (OFF));                                    \
    LDSM_X4(&(FA)[4],  aAddr[1][J] + (OFF));                                    \
    LDSM_X4(&(FA)[8],  aAddr[2][J] + (OFF));                                    \
    LDSM_X4(&(FA)[12], aAddr[3][J] + (OFF));                                    \
} while (0)

#define MMA_FRAGS64x32(FA, FB) do {                                             \
    _Pragma("unroll")                                                           \
    for (int mb_ = 0; mb_ < 4; ++mb_)                                           \
        _Pragma("unroll")                                                       \
        for (int nb_ = 0; nb_ < 4; ++nb_)                                       \
            mma16816(acc[mb_][nb_], &(FA)[mb_ * 4], (FB)[nb_], (FB)[4 + nb_]);  \
} while (0)

// =======================================================================
// BASE kernel: out = SiLU(x @ Wb). 4 producer + 8 consumer warps.
// =======================================================================
__global__ void __launch_bounds__(NTHREADS, 1)
kan_base_kernel(const float* __restrict__ x, float* __restrict__ out) {
    extern __shared__ char smem[];
    const uint32_t smem_base = smem_u32(smem);
    const int tid  = threadIdx.x;
    const int wid  = tid >> 5;
    const int lane = tid & 31;
    const int row_base = blockIdx.x * 128;

    if (wid < 4) {
        // ---- producers: 128 threads, 1 row x 64 cols each ----
        const int pr = tid;
        const float* xp = x + (size_t)(row_base + pr) * kD;
        const unsigned rowOff = (unsigned)(pr * 128);
        const unsigned rXor   = (unsigned)((pr & 7) << 4);

        float4 xq[16];
        auto loadX = [&](int c) {
            const float* p = xp + c * B_DC;
            #pragma unroll
            for (int j = 0; j < 16; ++j)
                xq[j] = *reinterpret_cast<const float4*>(p + j * 4);
        };
        auto produce = [&](uint32_t bufOff) {
            #pragma unroll
            for (int g = 0; g < 8; ++g) {
                union { __half2 h2[4]; uint4 u4; } st;
                st.h2[0] = __floats2half2_rn(xq[2*g].x,   xq[2*g].y);
                st.h2[1] = __floats2half2_rn(xq[2*g].z,   xq[2*g].w);
                st.h2[2] = __floats2half2_rn(xq[2*g+1].x, xq[2*g+1].y);
                st.h2[3] = __floats2half2_rn(xq[2*g+1].z, xq[2*g+1].w);
                unsigned off = rowOff + (unsigned)(g * 16);
                unsigned swz = off ^ rXor;
                *reinterpret_cast<uint4*>(smem + bufOff + swz) = st.u4;
            }
        };
        auto copyW = [&](int c, uint32_t bufOff) {
            const char* src = reinterpret_cast<const char*>(g_WbPack) + (size_t)c * 16384;
            #pragma unroll
            for (int j = 0; j < B_W_U4 / 128; ++j) {  // 8 per thread
                int i = pr + j * 128;
                cp_async16(smem_base + bufOff + B_AREG + i * 16, src + i * 16);
            }
            cp_async_commit();
        };

        copyW(0, 0);
        loadX(0);
        produce(0);
        cp_async_wait_all();
        __syncthreads();

        for (int c = 0; c < B_NCH; ++c) {
            if (c + 1 < B_NCH) {
                uint32_t bo = (uint32_t)(((c + 1) & 1) * B_BUF);
                copyW(c + 1, bo);
                loadX(c + 1);
                produce(bo);
                cp_async_wait_all();
            }
            __syncthreads();
        }
    } else {
        // ---- consumers: 8 warps (2/SMSP), 64x32 tiles, pipelined frags ----
        const int w  = wid - 4;
        const int mi = w & 1;
        const int ni = w >> 1;

        float acc[4][4][4];
        #pragma unroll
        for (int a = 0; a < 4; ++a)
            #pragma unroll
            for (int b = 0; b < 4; ++b)
                #pragma unroll
                for (int j = 0; j < 4; ++j) acc[a][b][j] = 0.f;

        const int aRowLocal  = (lane & 7) + ((lane >> 3) & 1) * 8;
        const uint32_t kbAhi = ((lane >> 4) & 1) * 16;
        uint32_t aAddr[4][4];
        #pragma unroll
        for (int mb = 0; mb < 4; ++mb) {
            int r = mi * 64 + mb * 16 + aRowLocal;
            uint32_t base = smem_base + (uint32_t)(r * 128);
            uint32_t ax   = (uint32_t)((r & 7) << 4);
            #pragma unroll
            for (int j = 0; j < 4; ++j)
                aAddr[mb][j] = base + (((uint32_t)(j * 32) + kbAhi) ^ ax);
        }
        uint32_t bAddr[8];
        {
            int rB = ni * 32 + lane;
            uint32_t base = smem_base + (uint32_t)B_AREG + (uint32_t)(rB * 128);
            uint32_t bx   = (uint32_t)((rB & 7) << 4);
            #pragma unroll
            for (int jb = 0; jb < 8; ++jb)
                bAddr[jb] = base + (((uint32_t)(jb * 16)) ^ bx);
        }

        __syncthreads();

        uint32_t fa0[16], fa1[16], fb0[8], fb1[8];
        for (int c = 0; c < B_NCH; ++c) {
            const uint32_t bo = (uint32_t)((c & 1) * B_BUF);
            LD_FRAGS64x32(bo, 0, fa0, fb0);
            LD_FRAGS64x32(bo, 1, fa1, fb1);  MMA_FRAGS64x32(fa0, fb0);
            LD_FRAGS64x32(bo, 2, fa0, fb0);  MMA_FRAGS64x32(fa1, fb1);
            LD_FRAGS64x32(bo, 3, fa1, fb1);  MMA_FRAGS64x32(fa0, fb0);
                                             MMA_FRAGS64x32(fa1, fb1);
            __syncthreads();
        }

        // epilogue: SiLU, store
        const int colBase = ni * 32 + (lane & 3) * 2;
        #pragma unroll
        for (int mb = 0; mb < 4; ++mb) {
            int row0 = row_base + mi * 64 + mb * 16 + (lane >> 2);
            #pragma unroll
            for (int nb = 0; nb < 4; ++nb) {
                int col = colBase + nb * 8;
                float z0 = acc[mb][nb][0], z1 = acc[mb][nb][1];
                float z2 = acc[mb][nb][2], z3 = acc[mb][nb][3];
                float2 v0, v1;
                v0.x = __fdividef(z0, 1.f + __expf(-z0));
                v0.y = __fdividef(z1, 1.f + __expf(-z1));
                v1.x = __fdividef(z2, 1.f + __expf(-z2));
                v1.y = __fdividef(z3, 1.f + __expf(-z3));
                *reinterpret_cast<float2*>(out + (size_t)row0 * kU + col)       = v0;
                *reinterpret_cast<float2*>(out + (size_t)(row0 + 8) * kU + col) = v1;
            }
        }
    }
}

// =======================================================================
// SPLINE kernel: out += einsum(rbf(x), Ws). 4 producer + 8 consumer warps.
// =======================================================================
__global__ void __launch_bounds__(NTHREADS, 1)
kan_spline_kernel(const float* __restrict__ x, float* __restrict__ out) {
    extern __shared__ char smem[];
    const uint32_t smem_base = smem_u32(smem);
    const int tid  = threadIdx.x;
    const int wid  = tid >> 5;
    const int lane = tid & 31;
    const int row_base = blockIdx.x * 128;

    const float E375p = 42.52108200006278f;    // e^{3.75}
    const float E125p = 3.4903429574597902f;   // e^{1.25}
    const float E125m = 0.2865047968601901f;   // e^{-1.25}
    const float E375m = 0.023517745856009107f; // e^{-3.75}

    if (wid < 4) {
        // ---- producers: 128 threads, 1 row x 32 cols each, 5 rbf streams ----
        const int pr = tid;
        const float* xp = x + (size_t)(row_base + pr) * kD;
        const unsigned rowOff = (unsigned)(pr * 128);
        const unsigned rXor   = (unsigned)((pr & 7) << 4);

        float4 xq[8];
        auto loadX = [&](int c) {
            const float* p = xp + c * S_DC;
            #pragma unroll
            for (int j = 0; j < 8; ++j)
                xq[j] = *reinterpret_cast<const float4*>(p + j * 4);
        };
        auto produce = [&](uint32_t bufOff) {
            #pragma unroll
            for (int g = 0; g < 4; ++g) {
                float xs[8];
                xs[0]=xq[2*g].x;   xs[1]=xq[2*g].y;   xs[2]=xq[2*g].z;   xs[3]=xq[2*g].w;
                xs[4]=xq[2*g+1].x; xs[5]=xq[2*g+1].y; xs[6]=xq[2*g+1].z; xs[7]=xq[2*g+1].w;
                union { __half2 h2[4]; uint4 u4; } st[5];
                #pragma unroll
                for (int e = 0; e < 8; e += 2) {
                    float a0 = xs[e] + 1.f, a1 = xs[e+1] + 1.f;
                    float y0a = __expf(-5.f * a0 * a0);
                    float y0b = __expf(-5.f * a1 * a1);
                    float ta  = __expf(5.f * xs[e]);
                    float tb  = __expf(5.f * xs[e+1]);
                    float y1a = y0a * ta * E375p, y1b = y0b * tb * E375p;
                    float y2a = y1a * ta * E125p, y2b = y1b * tb * E125p;
                    float y3a = y2a * ta * E125m, y3b = y2b * tb * E125m;
                    float y4a = y3a * ta * E375m, y4b = y3b * tb * E375m;
                    int j = e >> 1;
                    st[0].h2[j] = __floats2half2_rn(y0a, y0b);
                    st[1].h2[j] = __floats2half2_rn(y1a, y1b);
                    st[2].h2[j] = __floats2half2_rn(y2a, y2b);
                    st[3].h2[j] = __floats2half2_rn(y3a, y3b);
                    st[4].h2[j] = __floats2half2_rn(y4a, y4b);
                }
                #pragma unroll
                for (int s = 0; s < 5; ++s) {
                    int p = s >> 1, slo = s & 1;
                    unsigned off = rowOff + (unsigned)(slo * 64 + g * 16);
                    unsigned swz = off ^ rXor;
                    *reinterpret_cast<uint4*>(smem + bufOff + p * PAIR_BYTES + swz)
                        = st[s].u4;
                }
            }
        };
        auto copyW = [&](int c, uint32_t bufOff) {
            const char* src = reinterpret_cast<const char*>(g_WsPack) +
                              (size_t)c * (3 * 16384);
            #pragma unroll
            for (int j = 0; j < S_W_U4 / 128; ++j) {  // 24 per thread
                int i = pr + j * 128;
                cp_async16(smem_base + bufOff + S_AREG + i * 16, src + i * 16);
            }
            cp_async_commit();
        };

        copyW(0, 0);
        loadX(0);
        produce(0);
        cp_async_wait_all();
        __syncthreads();

        for (int c = 0; c < S_NCH; ++c) {
            if (c + 1 < S_NCH) {
                uint32_t bo = (uint32_t)(((c + 1) & 1) * S_BUF);
                copyW(c + 1, bo);
                loadX(c + 1);
                produce(bo);
                cp_async_wait_all();
            }
            __syncthreads();
        }
    } else {
        // ---- consumers: 8 warps (2/SMSP), 64x32 tiles, pipelined frags ----
        const int w  = wid - 4;
        const int mi = w & 1;
        const int ni = w >> 1;

        float acc[4][4][4];
        #pragma unroll
        for (int a = 0; a < 4; ++a)
            #pragma unroll
            for (int b = 0; b < 4; ++b)
                #pragma unroll
                for (int j = 0; j < 4; ++j) acc[a][b][j] = 0.f;

        const int aRowLocal  = (lane & 7) + ((lane >> 3) & 1) * 8;
        const uint32_t kbAhi = ((lane >> 4) & 1) * 16;
        uint32_t aAddr[4][4];
        #pragma unroll
        for (int mb = 0; mb < 4; ++mb) {
            int r = mi * 64 + mb * 16 + aRowLocal;
            uint32_t base = smem_base + (uint32_t)(r * 128);
            uint32_t ax   = (uint32_t)((r & 7) << 4);
            #pragma unroll
            for (int j = 0; j < 4; ++j)
                aAddr[mb][j] = base + (((uint32_t)(j * 32) + kbAhi) ^ ax);
        }
        uint32_t bAddr[8];
        {
            int rB = ni * 32 + lane;
            uint32_t base = smem_base + (uint32_t)S_AREG + (uint32_t)(rB * 128);
            uint32_t bx   = (uint32_t)((rB & 7) << 4);
            #pragma unroll
            for (int jb = 0; jb < 8; ++jb)
                bAddr[jb] = base + (((uint32_t)(jb * 16)) ^ bx);
        }

        __syncthreads();

        // step T (0..9): stream s = T/2, kk = T&1; pair p = s>>1; j = (s&1)*2+kk
#define S_LD(T, FA, FB) do {                                                    \
        constexpr int s_ = (T) / 2, kk_ = (T) & 1;                              \
        constexpr uint32_t pOff_ = (uint32_t)((s_ >> 1) * PAIR_BYTES);          \
        constexpr int j_ = (s_ & 1) * 2 + kk_;                                  \
        LD_FRAGS64x32(bo + pOff_, j_, FA, FB);                                  \
} while (0)

        uint32_t fa0[16], fa1[16], fb0[8], fb1[8];
        for (int c = 0; c < S_NCH; ++c) {
            const uint32_t bo = (uint32_t)((c & 1) * S_BUF);
            S_LD(0, fa0, fb0);
            S_LD(1, fa1, fb1);  MMA_FRAGS64x32(fa0, fb0);
            S_LD(2, fa0, fb0);  MMA_FRAGS64x32(fa1, fb1);
            S_LD(3, fa1, fb1);  MMA_FRAGS64x32(fa0, fb0);
            S_LD(4, fa0, fb0);  MMA_FRAGS64x32(fa1, fb1);
            S_LD(5, fa1, fb1);  MMA_FRAGS64x32(fa0, fb0);
            S_LD(6, fa0, fb0);  MMA_FRAGS64x32(fa1, fb1);
            S_LD(7, fa1, fb1);  MMA_FRAGS64x32(fa0, fb0);
            S_LD(8, fa0, fb0);  MMA_FRAGS64x32(fa1, fb1);
            S_LD(9, fa1, fb1);  MMA_FRAGS64x32(fa0, fb0);
                                MMA_FRAGS64x32(fa1, fb1);
            __syncthreads();
        }
#undef S_LD

        // epilogue: out += spline
        const int colBase = ni * 32 + (lane & 3) * 2;
        #pragma unroll
        for (int mb = 0; mb < 4; ++mb) {
            int row0 = row_base + mi * 64 + mb * 16 + (lane >> 2);
            #pragma unroll
            for (int nb = 0; nb < 4; ++nb) {
                int col = colBase + nb * 8;
                float2* p0 = reinterpret_cast<float2*>(out + (size_t)row0 * kU + col);
                float2* p1 = reinterpret_cast<float2*>(out + (size_t)(row0 + 8) * kU + col);
                float2 v0 = *p0, v1 = *p1;
                v0.x += acc[mb][nb][0]; v0.y += acc[mb][nb][1];
                v1.x += acc[mb][nb][2]; v1.y += acc[mb][nb][3];
                *p0 = v0; *p1 = v1;
            }
        }
    }
}

// ---------------- launch ----------------
extern "C" void kernel_launch(void* const* d_in, const int* in_sizes, int n_in,
                              void* d_out, int out_size) {
    (void)in_sizes; (void)n_in; (void)out_size;
    const float* x  = (const float*)d_in[0];
    const float* bw = (const float*)d_in[1];
    const float* sw = (const float*)d_in[2];
    float* out = (float*)d_out;

    cudaFuncSetAttribute(kan_base_kernel,
                         cudaFuncAttributeMaxDynamicSharedMemorySize, B_SMEM);
    cudaFuncSetAttribute(kan_spline_kernel,
                         cudaFuncAttributeMaxDynamicSharedMemorySize, S_SMEM);

    kan_prep_weights<<<(131072 + 786432) / 256, 256>>>(bw, sw);
    kan_base_kernel<<<kB / 128, NTHREADS, B_SMEM>>>(x, out);
    kan_spline_kernel<<<kB / 128, NTHREADS, S_SMEM>>>(x, out);
}

// round 12
// speedup vs baseline: 1.3474x; 1.0982x over previous
#include <cuda_runtime.h>
#include <cuda_fp16.h>
#include <cstdint>

#define DEV_INLINE __device__ __forceinline__

// ---------------- problem sizes ----------------
static constexpr int kB = 16384;
static constexpr int kD = 1024;
static constexpr int kU = 128;

// ---------------- tiling ----------------
static constexpr int DC    = 32;            // K per chunk
static constexpr int NCH   = kD / DC;       // 32 chunks
static constexpr int PAIRS = 3;             // stream pairs (0,1),(2,3),(4,5)
static constexpr int PAIR_BYTES = 128 * 128;           // 128 rows x 128B
static constexpr int HALF_BUF   = PAIRS * PAIR_BYTES;  // 49152 (A region or W region)
static constexpr int BUF_BYTES  = 2 * HALF_BUF;        // 98304 per buffer
static constexpr int SMEM_TOTAL = 2 * BUF_BYTES;       // 196608 double-buffered

static constexpr int W_HALVES = NCH * PAIRS * 8192;    // 786432 fp16
static constexpr int W_U4_PER_CHUNK = PAIRS * 8192 * 2 / 16;  // 3072 uint4

static constexpr int NTHREADS = 384;   // 4 producer warps (0-3) + 8 consumer warps (4-11)

// prepacked, SW128-swizzled fp16 weights: [chunk32][pair][128 rows][128B (2 streams)]
__device__ __half g_Wpack[W_HALVES];

// ---------------- PTX helpers ----------------
DEV_INLINE uint32_t smem_u32(const void* p) {
    uint32_t a;
    asm("{ .reg .u64 t; cvta.to.shared.u64 t, %1; cvt.u32.u64 %0, t; }" : "=r"(a) : "l"(p));
    return a;
}

#define LDSM_X4(r, addr)                                                        \
    asm volatile("ldmatrix.sync.aligned.m8n8.x4.shared.b16 {%0,%1,%2,%3}, [%4];"\
                 : "=r"((r)[0]), "=r"((r)[1]), "=r"((r)[2]), "=r"((r)[3])       \
                 : "r"(addr))

DEV_INLINE void mma16816(float* d, const uint32_t* a, uint32_t b0, uint32_t b1) {
    asm volatile(
        "mma.sync.aligned.m16n8k16.row.col.f32.f16.f16.f32 "
        "{%0,%1,%2,%3}, {%4,%5,%6,%7}, {%8,%9}, {%0,%1,%2,%3};"
        : "+f"(d[0]), "+f"(d[1]), "+f"(d[2]), "+f"(d[3])
        : "r"(a[0]), "r"(a[1]), "r"(a[2]), "r"(a[3]), "r"(b0), "r"(b1));
}

DEV_INLINE void cp_async16(uint32_t smem_dst, const void* gsrc) {
    asm volatile("cp.async.cg.shared.global [%0], [%1], 16;"
                 :: "r"(smem_dst), "l"(gsrc) : "memory");
}
DEV_INLINE void cp_async_commit() { asm volatile("cp.async.commit_group;" ::: "memory"); }
DEV_INLINE void cp_async_wait_all() { asm volatile("cp.async.wait_group 0;" ::: "memory"); }

// ---------------- weight prep: fp32 -> fp16, pair-interleaved + SW128 ----------------
__global__ void kan_prep_weights(const float* __restrict__ bw,
                                 const float* __restrict__ sw) {
    int idx = blockIdx.x * blockDim.x + threadIdx.x;
    if (idx >= W_HALVES) return;
    int hw  = idx & 63;            // half within 128B row
    int slo = hw >> 5;             // stream half (0/1)
    int k   = hw & 31;             // K within chunk
    int n   = (idx >> 6) & 127;    // output unit (B row)
    int t3  = idx >> 13;           // c*3 + p
    int p   = t3 % 3;
    int c   = t3 / 3;
    int s   = p * 2 + slo;         // stream 0..5
    int i   = c * DC + k;          // feature index
    float v = (s == 0) ? bw[i * kU + n]
                       : sw[(size_t)(i * kU + n) * 8 + (s - 1)];
    unsigned off = (unsigned)(n * 128 + slo * 64 + k * 2);
    unsigned swz = off ^ ((off >> 3) & 0x70);
    g_Wpack[(size_t)t3 * 8192 + (swz >> 1)] = __float2half(v);
}

// ---- consumer step macro (T literal): 6 LDSM + 16 MMA, single frag set ----
#define CSTEP(T) do {                                                           \
    constexpr int s_ = (T) % 6, kk_ = (T) / 6;                                  \
    constexpr int p_ = s_ >> 1, slo_ = s_ & 1;                                  \
    constexpr uint32_t pOff_ = (uint32_t)(p_ * PAIR_BYTES);                     \
    constexpr uint32_t kbC_  = (uint32_t)(slo_ * 64 + kk_ * 32);                \
    uint32_t fa_[16], fb_[8];                                                   \
    LDSM_X4(&fb_[0], bBase + pOff_ + bOff + ((kbC_ + 0u)  ^ bXor));             \
    LDSM_X4(&fb_[4], bBase + pOff_ + bOff + ((kbC_ + 16u) ^ bXor));             \
    {                                                                           \
        const uint32_t kbA_ = kbC_ + kbAhi;                                     \
        _Pragma("unroll")                                                       \
        for (int mb_ = 0; mb_ < 4; ++mb_)                                       \
            LDSM_X4(&fa_[mb_ * 4],                                              \
                    aBase + pOff_ + aOff[mb_] + (kbA_ ^ aXor[mb_]));            \
    }                                                                           \
    if (s_ == 0) {                                                              \
        _Pragma("unroll")                                                       \
        for (int mb_ = 0; mb_ < 4; ++mb_)                                       \
            _Pragma("unroll")                                                   \
            for (int nb_ = 0; nb_ < 4; ++nb_)                                   \
                mma16816(acc0[mb_][nb_], &fa_[mb_ * 4], fb_[nb_], fb_[4 + nb_]);\
    } else {                                                                    \
        _Pragma("unroll")                                                       \
        for (int mb_ = 0; mb_ < 4; ++mb_)                                       \
            _Pragma("unroll")                                                   \
            for (int nb_ = 0; nb_ < 4; ++nb_)                                   \
                mma16816(acc1[mb_][nb_], &fa_[mb_ * 4], fb_[nb_], fb_[4 + nb_]);\
    }                                                                           \
} while (0)

// ---------------- main fused kernel (warp-specialized, staggered consumers) ----------------
__global__ void __launch_bounds__(NTHREADS, 1)
kan_main_kernel(const float* __restrict__ x, float* __restrict__ out) {
    extern __shared__ char smem[];
    const uint32_t smem_base = smem_u32(smem);
    const int tid  = threadIdx.x;
    const int wid  = tid >> 5;
    const int lane = tid & 31;
    const int row_base = blockIdx.x * 128;

    // rbf chain constants
    const float E375p = 42.52108200006278f;    // e^{3.75}
    const float E125p = 3.4903429574597902f;   // e^{1.25}
    const float E125m = 0.2865047968601901f;   // e^{-1.25}
    const float E375m = 0.023517745856009107f; // e^{-3.75}

    if (wid < 4) {
        // ============ PRODUCER warps (4 warps = 128 threads, 1 row each) ============
        const int pr = tid;                        // 0..127
        const float* xp = x + (size_t)(row_base + pr) * kD;
        const uint32_t aSw = (uint32_t)((pr & 7) << 4);

        auto produce = [&](int c, uint32_t aRegionOff) {
            const float* xc = xp + c * DC;
            float4 xq[8];
            #pragma unroll
            for (int j = 0; j < 8; ++j)
                xq[j] = *reinterpret_cast<const float4*>(xc + j * 4);
            #pragma unroll
            for (int g = 0; g < 4; ++g) {
                float xs[8];
                xs[0]=xq[2*g].x;   xs[1]=xq[2*g].y;   xs[2]=xq[2*g].z;   xs[3]=xq[2*g].w;
                xs[4]=xq[2*g+1].x; xs[5]=xq[2*g+1].y; xs[6]=xq[2*g+1].z; xs[7]=xq[2*g+1].w;
                union { __half2 h2[4]; uint4 u4; } st[6];
                #pragma unroll
                for (int e = 0; e < 8; e += 2) {
                    float a0 = xs[e] + 1.f, a1 = xs[e+1] + 1.f;
                    float y0a = __expf(-5.f * a0 * a0);
                    float y0b = __expf(-5.f * a1 * a1);
                    float ta  = __expf(5.f * xs[e]);
                    float tb  = __expf(5.f * xs[e+1]);
                    float y1a = y0a * ta * E375p, y1b = y0b * tb * E375p;
                    float y2a = y1a * ta * E125p, y2b = y1b * tb * E125p;
                    float y3a = y2a * ta * E125m, y3b = y2b * tb * E125m;
                    float y4a = y3a * ta * E375m, y4b = y3b * tb * E375m;
                    int j = e >> 1;
                    st[0].h2[j] = __floats2half2_rn(xs[e], xs[e+1]);
                    st[1].h2[j] = __floats2half2_rn(y0a, y0b);
                    st[2].h2[j] = __floats2half2_rn(y1a, y1b);
                    st[3].h2[j] = __floats2half2_rn(y2a, y2b);
                    st[4].h2[j] = __floats2half2_rn(y3a, y3b);
                    st[5].h2[j] = __floats2half2_rn(y4a, y4b);
                }
                #pragma unroll
                for (int s = 0; s < 6; ++s) {
                    int p = s >> 1, slo = s & 1;
                    unsigned off = (unsigned)(pr * 128 + slo * 64 + g * 16);
                    unsigned swz = off ^ aSw;
                    *reinterpret_cast<uint4*>(smem + aRegionOff + p * PAIR_BYTES + swz)
                        = st[s].u4;
                }
            }
        };

        auto copyW = [&](int c, uint32_t wRegion) {
            const char* src = reinterpret_cast<const char*>(g_Wpack) +
                              (size_t)c * (PAIRS * 8192 * 2);
            #pragma unroll
            for (int j = 0; j < W_U4_PER_CHUNK / 128; ++j) {  // 24 per thread
                int i = pr + j * 128;
                cp_async16(wRegion + i * 16, src + i * 16);
            }
            cp_async_commit();
        };

        // prologue: chunk 0 -> buffer 0
        copyW(0, smem_base + HALF_BUF);
        produce(0, 0);
        cp_async_wait_all();
        __syncthreads();

        for (int c = 0; c < NCH; ++c) {
            if (c + 1 < NCH) {
                const uint32_t bufOff = (uint32_t)(((c + 1) & 1) * BUF_BYTES);
                copyW(c + 1, smem_base + bufOff + HALF_BUF);
                produce(c + 1, bufOff);
                cp_async_wait_all();
            }
            __syncthreads();
        }
    } else {
        // ============ CONSUMER warps (8, hi-wid): 64x32 tiles, staggered ============
        const int w  = wid - 4;        // 0..7
        const int mi = w & 1;          // rows mi*64
        const int ni = w >> 1;         // cols ni*32

        float acc0[4][4][4], acc1[4][4][4];
        #pragma unroll
        for (int a = 0; a < 4; ++a)
            #pragma unroll
            for (int b = 0; b < 4; ++b)
                #pragma unroll
                for (int j = 0; j < 4; ++j) { acc0[a][b][j] = 0.f; acc1[a][b][j] = 0.f; }

        const int aRowLocal  = (lane & 7) + ((lane >> 3) & 1) * 8;
        const uint32_t kbAhi = ((lane >> 4) & 1) * 16;
        uint32_t aOff[4], aXor[4];
        #pragma unroll
        for (int mb = 0; mb < 4; ++mb) {
            int r = mi * 64 + mb * 16 + aRowLocal;
            aOff[mb] = (uint32_t)(r * 128);
            aXor[mb] = (uint32_t)((r & 7) << 4);
        }
        const int rB = ni * 32 + lane;
        const uint32_t bOff = (uint32_t)(rB * 128);
        const uint32_t bXor = (uint32_t)((rB & 7) << 4);

        // stagger: one warp of each SMSP pair starts the (commutative) step
        // sequence at step 6, anti-phasing LDSM bursts against MMA bursts
        const bool phase2 = (wid >= 8);

        __syncthreads();  // matches producer prologue sync

        for (int c = 0; c < NCH; ++c) {
            const uint32_t aBase = smem_base + (uint32_t)((c & 1) * BUF_BYTES);
            const uint32_t bBase = aBase + (uint32_t)HALF_BUF;

            if (!phase2) {
                CSTEP(0);  CSTEP(1);  CSTEP(2);  CSTEP(3);  CSTEP(4);  CSTEP(5);
                CSTEP(6);  CSTEP(7);  CSTEP(8);  CSTEP(9);  CSTEP(10); CSTEP(11);
            } else {
                CSTEP(6);  CSTEP(7);  CSTEP(8);  CSTEP(9);  CSTEP(10); CSTEP(11);
                CSTEP(0);  CSTEP(1);  CSTEP(2);  CSTEP(3);  CSTEP(4);  CSTEP(5);
            }
            __syncthreads();
        }

        // epilogue: SiLU(base) + spline
        const int colBase = ni * 32 + (lane & 3) * 2;
        #pragma unroll
        for (int mb = 0; mb < 4; ++mb) {
            int row0 = row_base + mi * 64 + mb * 16 + (lane >> 2);
            #pragma unroll
            for (int nb = 0; nb < 4; ++nb) {
                int col = colBase + nb * 8;
                float z0 = acc0[mb][nb][0], z1 = acc0[mb][nb][1];
                float z2 = acc0[mb][nb][2], z3 = acc0[mb][nb][3];
                float2 v0, v1;
                v0.x = __fdividef(z0, 1.f + __expf(-z0)) + acc1[mb][nb][0];
                v0.y = __fdividef(z1, 1.f + __expf(-z1)) + acc1[mb][nb][1];
                v1.x = __fdividef(z2, 1.f + __expf(-z2)) + acc1[mb][nb][2];
                v1.y = __fdividef(z3, 1.f + __expf(-z3)) + acc1[mb][nb][3];
                *reinterpret_cast<float2*>(out + (size_t)row0 * kU + col)       = v0;
                *reinterpret_cast<float2*>(out + (size_t)(row0 + 8) * kU + col) = v1;
            }
        }
    }
}

// ---------------- launch ----------------
extern "C" void kernel_launch(void* const* d_in, const int* in_sizes, int n_in,
                              void* d_out, int out_size) {
    (void)in_sizes; (void)n_in; (void)out_size;
    const float* x  = (const float*)d_in[0];
    const float* bw = (const float*)d_in[1];
    const float* sw = (const float*)d_in[2];
    float* out = (float*)d_out;

    cudaFuncSetAttribute(kan_main_kernel,
                         cudaFuncAttributeMaxDynamicSharedMemorySize, SMEM_TOTAL);

    kan_prep_weights<<<(W_HALVES + 255) / 256, 256>>>(bw, sw);
    kan_main_kernel<<<kB / 128, NTHREADS, SMEM_TOTAL>>>(x, out);
}